// round 2
// baseline (speedup 1.0000x reference)
#include <cuda_runtime.h>
#include <cstdint>

// Conv2DUF: y = im2col(x) @ W + b
//   x      : [32, 128, 56, 56] fp32 (NCHW)
//   weight : [128*3*3, 256]    fp32  (k = c*9 + kh*3 + kw major, cout contiguous)
//   bias   : [256]             fp32
//   out    : [32, 256, 56, 56] fp32
//
// Implicit GEMM: M = 32*56*56 = 100352, N = 256, K = 1152.
// Tiles: BM=64 (pixels), BN=128 (cout), BK=16. 256 threads, 4x8 regs/thread,
// accumulators packed as f32x2 pairs for FFMA2 (fma.rn.f32x2).

namespace {
constexpr int C_IN  = 128;
constexpr int C_OUT = 256;
constexpr int Hc = 56, Wc = 56;
constexpr int HW = Hc * Wc;          // 3136 = 49*64
constexpr int BM = 64, BN = 128, BK = 16;
constexpr int KTOT   = C_IN * 9;     // 1152
constexpr int KTILES = KTOT / BK;    // 72
}

__device__ __forceinline__ void cp_async4(uint32_t dst, const void* src, int sz) {
    asm volatile("cp.async.ca.shared.global [%0], [%1], 4, %2;\n"
                 :: "r"(dst), "l"(src), "r"(sz));
}
__device__ __forceinline__ void cp_async16(uint32_t dst, const void* src) {
    asm volatile("cp.async.cg.shared.global [%0], [%1], 16;\n"
                 :: "r"(dst), "l"(src));
}

__global__ __launch_bounds__(256, 2)
void conv2duf_kernel(const float* __restrict__ x,
                     const float* __restrict__ w,
                     const float* __restrict__ bias,
                     float* __restrict__ out)
{
    __shared__ float As[2][BK][BM];   // 2 * 4 KB
    __shared__ float Bs[2][BK][BN];   // 2 * 8 KB

    const int tid = threadIdx.x;
    const int bx  = blockIdx.x;              // 0..1567  (M tiles)
    const int bn0 = blockIdx.y * BN;         // 0 or 128 (N tiles)

    // ---- A (im2col) load mapping: 4 elems/thread, ml fast for coalescing ----
    const int ml  = tid & 63;                // pixel within tile
    const int kkb = tid >> 6;                // 0..3 -> kk = kkb + 4j
    const int p    = bx * BM + ml;
    const int nimg = p / HW;                 // tile never crosses an image
    const int rem  = p - nimg * HW;
    const int ypix = rem / Wc;
    const int xpix = rem - ypix * Wc;
    const float* xbase = x + (size_t)nimg * C_IN * HW;

    // ---- compute mapping: 4 m x (4 + 4) n per thread ----
    const int tm = tid >> 4;                 // 0..15 -> m0 = tm*4
    const int tn = tid & 15;                 // 0..15 -> n0 = tn*4 (and +64)
    const int m0 = tm * 4;
    const int n0 = tn * 4;

    const uint32_t sA = (uint32_t)__cvta_generic_to_shared(&As[0][0][0]);
    const uint32_t sB = (uint32_t)__cvta_generic_to_shared(&Bs[0][0][0]);

    // bias preload (co offsets relative to bn0+n0: 0..3, 64..67)
    float bsv[8];
#pragma unroll
    for (int cj = 0; cj < 8; cj++) {
        int off = (cj < 4) ? cj : cj + 60;
        bsv[cj] = bias[bn0 + n0 + off];
    }

    unsigned long long acc[16];
#pragma unroll
    for (int i = 0; i < 16; i++) acc[i] = 0ull;

    auto issue = [&](int kt, int buf) {
        const int k0 = kt * BK;
        // A tile (im2col gather, zero-fill padding via src-size=0)
#pragma unroll
        for (int j = 0; j < 4; j++) {
            int kk = kkb + j * 4;
            int k  = k0 + kk;
            int c  = k / 9;
            int r  = k - c * 9;
            int kh = r / 3;
            int kw = r - kh * 3;
            int iy = ypix + kh - 1;
            int ix = xpix + kw - 1;
            bool ok = ((unsigned)iy < (unsigned)Hc) && ((unsigned)ix < (unsigned)Wc);
            const float* src = ok ? (xbase + c * HW + iy * Wc + ix) : xbase;
            cp_async4(sA + buf * 4096 + kk * (BM * 4) + ml * 4, src, ok ? 4 : 0);
        }
        // B tile: weight rows are cout-contiguous -> direct float4 copies
#pragma unroll
        for (int j = 0; j < 2; j++) {
            int f  = tid + j * 256;          // 512 float4 total
            int kk = f >> 5;
            int nj = f & 31;
            const float* src = w + (size_t)(k0 + kk) * C_OUT + bn0 + nj * 4;
            cp_async16(sB + buf * 8192 + kk * (BN * 4) + nj * 16, src);
        }
        asm volatile("cp.async.commit_group;\n" ::: "memory");
    };

    issue(0, 0);
    asm volatile("cp.async.wait_group 0;\n" ::: "memory");
    __syncthreads();

    for (int kt = 0; kt < KTILES; kt++) {
        const int buf = kt & 1;
        if (kt + 1 < KTILES) issue(kt + 1, buf ^ 1);

        const uint32_t aAddr = sA + buf * 4096 + m0 * 4;
        const uint32_t bAddr = sB + buf * 8192 + n0 * 4;
#pragma unroll
        for (int kk = 0; kk < BK; kk++) {
            float a0, a1, a2, a3;
            asm("ld.shared.v4.f32 {%0,%1,%2,%3}, [%4];"
                : "=f"(a0), "=f"(a1), "=f"(a2), "=f"(a3)
                : "r"(aAddr + kk * (BM * 4)));
            unsigned long long b0, b1, b2, b3;
            asm("ld.shared.v2.b64 {%0,%1}, [%2];"
                : "=l"(b0), "=l"(b1) : "r"(bAddr + kk * (BN * 4)));
            asm("ld.shared.v2.b64 {%0,%1}, [%2];"
                : "=l"(b2), "=l"(b3) : "r"(bAddr + kk * (BN * 4) + 64 * 4));
            unsigned ua0 = __float_as_uint(a0), ua1 = __float_as_uint(a1);
            unsigned ua2 = __float_as_uint(a2), ua3 = __float_as_uint(a3);
            unsigned long long ap0, ap1, ap2, ap3;
            asm("mov.b64 %0, {%1,%1};" : "=l"(ap0) : "r"(ua0));
            asm("mov.b64 %0, {%1,%1};" : "=l"(ap1) : "r"(ua1));
            asm("mov.b64 %0, {%1,%1};" : "=l"(ap2) : "r"(ua2));
            asm("mov.b64 %0, {%1,%1};" : "=l"(ap3) : "r"(ua3));
            unsigned long long ap[4] = {ap0, ap1, ap2, ap3};
#pragma unroll
            for (int mi = 0; mi < 4; mi++) {
                asm("fma.rn.f32x2 %0, %1, %2, %0;" : "+l"(acc[mi*4+0]) : "l"(ap[mi]), "l"(b0));
                asm("fma.rn.f32x2 %0, %1, %2, %0;" : "+l"(acc[mi*4+1]) : "l"(ap[mi]), "l"(b1));
                asm("fma.rn.f32x2 %0, %1, %2, %0;" : "+l"(acc[mi*4+2]) : "l"(ap[mi]), "l"(b2));
                asm("fma.rn.f32x2 %0, %1, %2, %0;" : "+l"(acc[mi*4+3]) : "l"(ap[mi]), "l"(b3));
            }
        }
        asm volatile("cp.async.wait_group 0;\n" ::: "memory");
        __syncthreads();
    }

    // ---- epilogue: unpack, add bias, float4 stores (pixels contiguous per cout) ----
    float cv[4][8];
#pragma unroll
    for (int mi = 0; mi < 4; mi++) {
#pragma unroll
        for (int pj = 0; pj < 4; pj++) {
            unsigned lo, hi;
            asm("mov.b64 {%0,%1}, %2;" : "=r"(lo), "=r"(hi) : "l"(acc[mi*4+pj]));
            int cj = (pj < 2) ? pj * 2 : 4 + (pj - 2) * 2;
            cv[mi][cj]     = __uint_as_float(lo);
            cv[mi][cj + 1] = __uint_as_float(hi);
        }
    }

    const int nimg0 = bx / 49;                 // tile's image
    const int remT  = (bx - nimg0 * 49) * BM;  // pixel offset within image
    float* obase = out + (size_t)nimg0 * C_OUT * HW + remT + m0;
#pragma unroll
    for (int cj = 0; cj < 8; cj++) {
        int off = (cj < 4) ? cj : cj + 60;
        int co  = bn0 + n0 + off;
        float4 v = make_float4(cv[0][cj] + bsv[cj], cv[1][cj] + bsv[cj],
                               cv[2][cj] + bsv[cj], cv[3][cj] + bsv[cj]);
        *reinterpret_cast<float4*>(obase + (size_t)co * HW) = v;
    }
}

extern "C" void kernel_launch(void* const* d_in, const int* in_sizes, int n_in,
                              void* d_out, int out_size) {
    const float* x    = (const float*)d_in[0];
    const float* w    = (const float*)d_in[1];
    const float* bias = (const float*)d_in[2];
    float* out        = (float*)d_out;
    dim3 grid(49 * 32, 2);   // 1568 M-tiles x 2 N-tiles
    conv2duf_kernel<<<grid, 256>>>(x, w, bias, out);
}

// round 4
// speedup vs baseline: 2.9304x; 2.9304x over previous
#include <cuda_runtime.h>
#include <cstdint>

// Conv2DUF via legacy mma.sync TF32 implicit GEMM (compute_103-safe, no tcgen05).
//   x: [32,128,56,56] f32   weight: [1152,256] f32   bias: [256]   out: [32,256,56,56]
// GEMM: M=100352 (pixels), N=256 (cout), K=1152 reordered k' = (kh*3+kw)*128 + c.
// Prepass: x -> NHWC tf32-rounded (g_xt), w -> [n][k'] tf32-rounded (g_wT).
// Main: CTA 128x128, BK=32, 8 warps x (32x64), mma.sync.m16n8k8.tf32, cp.async x2 buffers.

namespace {
constexpr int HW = 3136;        // 56*56
constexpr int KT = 36;          // 1152/32
}

__device__ float g_xt[32 * HW * 128];   // NHWC, tf32-rounded (51 MB)
__device__ float g_wT[256 * 1152];      // [cout][k'], tf32-rounded

__device__ __forceinline__ uint32_t s2u(const void* p) {
    uint32_t a;
    asm("{.reg .u64 t; cvta.to.shared.u64 t, %1; cvt.u32.u64 %0, t;}" : "=r"(a) : "l"(p));
    return a;
}
__device__ __forceinline__ uint32_t swz(uint32_t o) { return o ^ ((o >> 3) & 0x70); }
__device__ __forceinline__ void cp16(uint32_t dst, const void* src, int sz) {
    asm volatile("cp.async.cg.shared.global [%0], [%1], 16, %2;" :: "r"(dst), "l"(src), "r"(sz));
}
__device__ __forceinline__ float tf32rn(float v) {
    uint32_t u; asm("cvt.rn.tf32.f32 %0, %1;" : "=r"(u) : "f"(v));
    return __uint_as_float(u);
}
__device__ __forceinline__ void ldsm4(uint32_t* r, uint32_t addr) {
    asm volatile("ldmatrix.sync.aligned.m8n8.x4.shared.b16 {%0,%1,%2,%3}, [%4];"
                 : "=r"(r[0]), "=r"(r[1]), "=r"(r[2]), "=r"(r[3]) : "r"(addr));
}
__device__ __forceinline__ void mma8(float* c, const uint32_t* a, uint32_t b0, uint32_t b1) {
    asm volatile("mma.sync.aligned.m16n8k8.row.col.f32.tf32.tf32.f32 "
                 "{%0,%1,%2,%3},{%4,%5,%6,%7},{%8,%9},{%0,%1,%2,%3};"
                 : "+f"(c[0]), "+f"(c[1]), "+f"(c[2]), "+f"(c[3])
                 : "r"(a[0]), "r"(a[1]), "r"(a[2]), "r"(a[3]), "r"(b0), "r"(b1));
}

// ---- prepass 1: x NCHW -> g_xt NHWC, tf32-RN ----
__global__ void transpose_x_kernel(const float* __restrict__ x) {
    __shared__ float t[32][33];
    const int n = blockIdx.z, p0 = blockIdx.x * 32, c0 = blockIdx.y * 32;
    const int tx = threadIdx.x, ty = threadIdx.y;      // 32 x 8
    const float* xp = x + ((size_t)n * 128 + c0) * HW + p0;
#pragma unroll
    for (int i = ty; i < 32; i += 8)
        t[i][tx] = tf32rn(xp[(size_t)i * HW + tx]);
    __syncthreads();
    float* xo = g_xt + ((size_t)n * HW + p0) * 128 + c0;
#pragma unroll
    for (int i = ty; i < 32; i += 8)
        xo[(size_t)i * 128 + tx] = t[tx][i];
}

// ---- prepass 2: w[k][n] -> g_wT[n][k'], k' = r*128 + c (k = c*9 + r), tf32-RN ----
__global__ void transpose_w_kernel(const float* __restrict__ w) {
    __shared__ float t[32][33];
    const int kp0 = blockIdx.x * 32, n0 = blockIdx.y * 32;
    const int tx = threadIdx.x & 31, ty = threadIdx.x >> 5;
    for (int i = ty; i < 32; i += 8) {
        int kp = kp0 + i;
        int r = kp >> 7, c = kp & 127;
        t[i][tx] = tf32rn(w[(c * 9 + r) * 256 + n0 + tx]);
    }
    __syncthreads();
    for (int i = ty; i < 32; i += 8)
        g_wT[(size_t)(n0 + i) * 1152 + kp0 + tx] = t[tx][i];
}

// ---- main kernel ----
__global__ __launch_bounds__(256, 2)
void conv_mma_kernel(const float* __restrict__ bias, float* __restrict__ out) {
    extern __shared__ char smem[];
    const uint32_t sb = s2u(smem);          // A0 @0, A1 @16K, B0 @32K, B1 @48K
    const int tid = threadIdx.x, wid = tid >> 5, lid = tid & 31;
    const int bx = blockIdx.x;              // 784 M-tiles
    const int bn0 = blockIdx.y * 128;       // N tile

    // producer mapping: row = tid>>1 (0..127), qh selects 16B-chunk group
    const int arow = tid >> 1, qh = tid & 1;
    const int p = bx * 128 + arow;
    const int nimg = p / HW;
    const int rem = p - nimg * HW;
    const int yp = rem / 56, xp = rem - yp * 56;
    const float* xrow = g_xt + ((size_t)nimg * HW + (yp - 1) * 56 + (xp - 1)) * 128;
    const float* wrow = g_wT + (size_t)(bn0 + arow) * 1152;

    auto issue = [&](int kt, int buf) {
        const int r = kt >> 2;
        const int kh = r / 3, kw = r - kh * 3;
        const int cb = (kt & 3) * 32;
        const bool ok = ((unsigned)(yp + kh - 1) < 56u) && ((unsigned)(xp + kw - 1) < 56u);
        const float* asrc = ok ? (xrow + (kh * 56 + kw) * 128 + cb) : g_xt;
        const int sz = ok ? 16 : 0;
        const uint32_t ad = sb + buf * 16384;
        const uint32_t bd = sb + 32768 + buf * 16384;
        const float* bsrc = wrow + kt * 32;
#pragma unroll
        for (int j = 0; j < 4; j++) {
            int q = qh * 4 + j;
            cp16(ad + swz(arow * 128 + q * 16), asrc + (ok ? q * 4 : 0), sz);
            cp16(bd + swz(arow * 128 + q * 16), bsrc + q * 4, 16);
        }
        asm volatile("cp.async.commit_group;" ::: "memory");
    };

    issue(0, 0);
    issue(1, 1);

    float acc[2][8][4];
#pragma unroll
    for (int i = 0; i < 2; i++)
#pragma unroll
        for (int j = 0; j < 8; j++)
#pragma unroll
            for (int q = 0; q < 4; q++) acc[i][j][q] = 0.f;

    const int m0 = (wid & 3) * 32;          // warp m-base
    const int n0w = (wid >> 2) * 64;        // warp n-base
    const int rowA = lid & 15, colA = (lid >> 4) * 16;
    const int rowB = (lid & 7) | ((lid & 16) >> 1), colB = (lid & 8) * 2;

    for (int kt = 0; kt < KT; kt++) {
        if (kt < KT - 1) asm volatile("cp.async.wait_group 1;" ::: "memory");
        else             asm volatile("cp.async.wait_group 0;" ::: "memory");
        __syncthreads();
        const int buf = kt & 1;
        const uint32_t aT = sb + buf * 16384;
        const uint32_t bT = sb + 32768 + buf * 16384;
#pragma unroll
        for (int s = 0; s < 4; s++) {
            uint32_t a[2][4], b[4][4];
#pragma unroll
            for (int mi = 0; mi < 2; mi++)
                ldsm4(a[mi], aT + swz((m0 + mi * 16 + rowA) * 128 + s * 32 + colA));
#pragma unroll
            for (int nj = 0; nj < 4; nj++)
                ldsm4(b[nj], bT + swz((n0w + nj * 16 + rowB) * 128 + s * 32 + colB));
#pragma unroll
            for (int mi = 0; mi < 2; mi++)
#pragma unroll
                for (int ni = 0; ni < 8; ni++)
                    mma8(acc[mi][ni], a[mi], b[ni >> 1][(ni & 1) * 2], b[ni >> 1][(ni & 1) * 2 + 1]);
        }
        __syncthreads();
        if (kt + 2 < KT) issue(kt + 2, buf);
    }

    // ---- epilogue ----
    float bv[8][2];
#pragma unroll
    for (int ni = 0; ni < 8; ni++) {
        int co = bn0 + n0w + ni * 8 + (lid & 3) * 2;
        bv[ni][0] = bias[co];
        bv[ni][1] = bias[co + 1];
    }
#pragma unroll
    for (int mi = 0; mi < 2; mi++) {
        const int pg0 = bx * 128 + m0 + mi * 16 + (lid >> 2);
        const int pg1 = pg0 + 8;
        const int n0i = pg0 / HW, pix0 = pg0 - n0i * HW;
        const int n1i = pg1 / HW, pix1 = pg1 - n1i * HW;
        float* o0 = out + (size_t)n0i * 256 * HW + pix0;
        float* o1 = out + (size_t)n1i * 256 * HW + pix1;
#pragma unroll
        for (int ni = 0; ni < 8; ni++) {
            const int co = bn0 + n0w + ni * 8 + (lid & 3) * 2;
            o0[(size_t)co * HW]       = acc[mi][ni][0] + bv[ni][0];
            o0[(size_t)(co + 1) * HW] = acc[mi][ni][1] + bv[ni][1];
            o1[(size_t)co * HW]       = acc[mi][ni][2] + bv[ni][0];
            o1[(size_t)(co + 1) * HW] = acc[mi][ni][3] + bv[ni][1];
        }
    }
}

extern "C" void kernel_launch(void* const* d_in, const int* in_sizes, int n_in,
                              void* d_out, int out_size) {
    const float* x    = (const float*)d_in[0];
    const float* w    = (const float*)d_in[1];
    const float* bias = (const float*)d_in[2];
    float* out        = (float*)d_out;

    cudaFuncSetAttribute(conv_mma_kernel, cudaFuncAttributeMaxDynamicSharedMemorySize, 65536);

    transpose_x_kernel<<<dim3(98, 4, 32), dim3(32, 8)>>>(x);   // 3136/32 x 128/32 x 32
    transpose_w_kernel<<<dim3(36, 8), 256>>>(w);               // 1152 x 256
    conv_mma_kernel<<<dim3(784, 2), 256, 65536>>>(bias, out);
}

// round 5
// speedup vs baseline: 2.9974x; 1.0229x over previous
#include <cuda_runtime.h>
#include <cstdint>

// Conv2DUF via legacy mma.sync TF32 implicit GEMM (compute_103-safe).
//   x: [32,128,56,56] f32   weight: [1152,256] f32   bias: [256]   out: [32,256,56,56]
// GEMM: M=100352 (pixels), N=256 (cout), K=1152 reordered k' = (kh*3+kw)*128 + c.
// Prepass: x -> NHWC tf32-rounded (g_xt), w -> [n][k'] tf32-rounded (g_wT).
// Main: CTA 128x128, BK=32, 8 warps x (32x64), mma.sync.m16n8k8.tf32,
//       3-buffer cp.async ring, ONE __syncthreads per k-stage.

namespace {
constexpr int HW = 3136;        // 56*56
constexpr int KT = 36;          // 1152/32
constexpr int ABUF = 16384;     // one A stage (128 rows * 128B)
constexpr int BOFF = 3 * ABUF;  // B region starts after 3 A stages
constexpr int SMEM_DYN = 6 * ABUF;   // 96 KB
}

__device__ float g_xt[32 * HW * 128];   // NHWC, tf32-rounded (51 MB)
__device__ float g_wT[256 * 1152];      // [cout][k'], tf32-rounded

__device__ __forceinline__ uint32_t s2u(const void* p) {
    uint32_t a;
    asm("{.reg .u64 t; cvta.to.shared.u64 t, %1; cvt.u32.u64 %0, t;}" : "=r"(a) : "l"(p));
    return a;
}
__device__ __forceinline__ uint32_t swz(uint32_t o) { return o ^ ((o >> 3) & 0x70); }
__device__ __forceinline__ void cp16(uint32_t dst, const void* src, int sz) {
    asm volatile("cp.async.cg.shared.global [%0], [%1], 16, %2;" :: "r"(dst), "l"(src), "r"(sz));
}
__device__ __forceinline__ float tf32rn(float v) {
    uint32_t u; asm("cvt.rn.tf32.f32 %0, %1;" : "=r"(u) : "f"(v));
    return __uint_as_float(u);
}
__device__ __forceinline__ void ldsm4(uint32_t* r, uint32_t addr) {
    asm volatile("ldmatrix.sync.aligned.m8n8.x4.shared.b16 {%0,%1,%2,%3}, [%4];"
                 : "=r"(r[0]), "=r"(r[1]), "=r"(r[2]), "=r"(r[3]) : "r"(addr));
}
__device__ __forceinline__ void mma8(float* c, const uint32_t* a, uint32_t b0, uint32_t b1) {
    asm volatile("mma.sync.aligned.m16n8k8.row.col.f32.tf32.tf32.f32 "
                 "{%0,%1,%2,%3},{%4,%5,%6,%7},{%8,%9},{%0,%1,%2,%3};"
                 : "+f"(c[0]), "+f"(c[1]), "+f"(c[2]), "+f"(c[3])
                 : "r"(a[0]), "r"(a[1]), "r"(a[2]), "r"(a[3]), "r"(b0), "r"(b1));
}

// ---- prepass 1: x NCHW -> g_xt NHWC, tf32-RN ----
__global__ void transpose_x_kernel(const float* __restrict__ x) {
    __shared__ float t[32][33];
    const int n = blockIdx.z, p0 = blockIdx.x * 32, c0 = blockIdx.y * 32;
    const int tx = threadIdx.x, ty = threadIdx.y;      // 32 x 8
    const float* xp = x + ((size_t)n * 128 + c0) * HW + p0;
#pragma unroll
    for (int i = ty; i < 32; i += 8)
        t[i][tx] = tf32rn(xp[(size_t)i * HW + tx]);
    __syncthreads();
    float* xo = g_xt + ((size_t)n * HW + p0) * 128 + c0;
#pragma unroll
    for (int i = ty; i < 32; i += 8)
        xo[(size_t)i * 128 + tx] = t[tx][i];
}

// ---- prepass 2: w[k][n] -> g_wT[n][k'], k' = r*128 + c (k = c*9 + r), tf32-RN ----
__global__ void transpose_w_kernel(const float* __restrict__ w) {
    __shared__ float t[32][33];
    const int kp0 = blockIdx.x * 32, n0 = blockIdx.y * 32;
    const int tx = threadIdx.x & 31, ty = threadIdx.x >> 5;
    for (int i = ty; i < 32; i += 8) {
        int kp = kp0 + i;
        int r = kp >> 7, c = kp & 127;
        t[i][tx] = tf32rn(w[(c * 9 + r) * 256 + n0 + tx]);
    }
    __syncthreads();
    for (int i = ty; i < 32; i += 8)
        g_wT[(size_t)(n0 + i) * 1152 + kp0 + tx] = t[tx][i];
}

// ---- main kernel ----
__global__ __launch_bounds__(256, 2)
void conv_mma_kernel(const float* __restrict__ bias, float* __restrict__ out) {
    extern __shared__ char smem[];
    const uint32_t sb = s2u(smem);          // A stages @0,16K,32K; B stages @48K,64K,80K
    const int tid = threadIdx.x, wid = tid >> 5, lid = tid & 31;
    const int bx = blockIdx.x;              // 784 M-tiles
    const int bn0 = blockIdx.y * 128;       // N tile

    // producer mapping: row = tid>>1 (0..127), qh selects 16B-chunk pair group
    const int arow = tid >> 1, qh = tid & 1;
    const int p = bx * 128 + arow;
    const int nimg = p / HW;
    const int rem = p - nimg * HW;
    const int yp = rem / 56, xp = rem - yp * 56;
    const float* xrow = g_xt + ((size_t)nimg * HW + (yp - 1) * 56 + (xp - 1)) * 128;
    const float* wrow = g_wT + (size_t)(bn0 + arow) * 1152;

    // precomputed per-thread swizzled SMEM offsets (kt-invariant)
    uint32_t dsto[4];
#pragma unroll
    for (int j = 0; j < 4; j++)
        dsto[j] = swz(arow * 128 + (qh * 4 + j) * 16);

    auto issue = [&](int kt, int buf) {
        const int r = kt >> 2;
        const int kh = r / 3, kw = r - kh * 3;
        const int cb = (kt & 3) * 32;
        const bool ok = ((unsigned)(yp + kh - 1) < 56u) && ((unsigned)(xp + kw - 1) < 56u);
        const float* asrc = ok ? (xrow + (kh * 56 + kw) * 128 + cb) : g_xt;
        const int sz = ok ? 16 : 0;
        const uint32_t ad = sb + buf * ABUF;
        const uint32_t bd = sb + BOFF + buf * ABUF;
        const float* bsrc = wrow + kt * 32;
#pragma unroll
        for (int j = 0; j < 4; j++) {
            int q = qh * 4 + j;
            cp16(ad + dsto[j], asrc + (ok ? q * 4 : 0), sz);
            cp16(bd + dsto[j], bsrc + q * 4, 16);
        }
        asm volatile("cp.async.commit_group;" ::: "memory");
    };

    issue(0, 0);
    issue(1, 1);

    float acc[2][8][4];
#pragma unroll
    for (int i = 0; i < 2; i++)
#pragma unroll
        for (int j = 0; j < 8; j++)
#pragma unroll
            for (int q = 0; q < 4; q++) acc[i][j][q] = 0.f;

    const int m0 = (wid & 3) * 32;          // warp m-base
    const int n0w = (wid >> 2) * 64;        // warp n-base
    const int rowA = lid & 15, colA = (lid >> 4) * 16;
    const int rowB = (lid & 7) | ((lid & 16) >> 1), colB = (lid & 8) * 2;

    int buf = 0, pbuf = 2;                  // compute buffer, prefetch buffer (kt+2)%3
    for (int kt = 0; kt < KT; kt++) {
        if (kt < KT - 1) asm volatile("cp.async.wait_group 1;" ::: "memory");
        else             asm volatile("cp.async.wait_group 0;" ::: "memory");
        __syncthreads();
        if (kt + 2 < KT) issue(kt + 2, pbuf);

        const uint32_t aT = sb + buf * ABUF;
        const uint32_t bT = sb + BOFF + buf * ABUF;
#pragma unroll
        for (int s = 0; s < 4; s++) {
            uint32_t a[2][4], b[4][4];
#pragma unroll
            for (int mi = 0; mi < 2; mi++)
                ldsm4(a[mi], aT + swz((m0 + mi * 16 + rowA) * 128 + s * 32 + colA));
#pragma unroll
            for (int nj = 0; nj < 4; nj++)
                ldsm4(b[nj], bT + swz((n0w + nj * 16 + rowB) * 128 + s * 32 + colB));
#pragma unroll
            for (int mi = 0; mi < 2; mi++)
#pragma unroll
                for (int ni = 0; ni < 8; ni++)
                    mma8(acc[mi][ni], a[mi], b[ni >> 1][(ni & 1) * 2], b[ni >> 1][(ni & 1) * 2 + 1]);
        }
        buf  = (buf == 2)  ? 0 : buf + 1;
        pbuf = (pbuf == 2) ? 0 : pbuf + 1;
    }

    // ---- epilogue ----
    float bv[8][2];
#pragma unroll
    for (int ni = 0; ni < 8; ni++) {
        int co = bn0 + n0w + ni * 8 + (lid & 3) * 2;
        bv[ni][0] = bias[co];
        bv[ni][1] = bias[co + 1];
    }
#pragma unroll
    for (int mi = 0; mi < 2; mi++) {
        const int pg0 = bx * 128 + m0 + mi * 16 + (lid >> 2);
        const int pg1 = pg0 + 8;
        const int n0i = pg0 / HW, pix0 = pg0 - n0i * HW;
        const int n1i = pg1 / HW, pix1 = pg1 - n1i * HW;
        float* o0 = out + (size_t)n0i * 256 * HW + pix0;
        float* o1 = out + (size_t)n1i * 256 * HW + pix1;
#pragma unroll
        for (int ni = 0; ni < 8; ni++) {
            const int co = bn0 + n0w + ni * 8 + (lid & 3) * 2;
            o0[(size_t)co * HW]       = acc[mi][ni][0] + bv[ni][0];
            o0[(size_t)(co + 1) * HW] = acc[mi][ni][1] + bv[ni][1];
            o1[(size_t)co * HW]       = acc[mi][ni][2] + bv[ni][0];
            o1[(size_t)(co + 1) * HW] = acc[mi][ni][3] + bv[ni][1];
        }
    }
}

extern "C" void kernel_launch(void* const* d_in, const int* in_sizes, int n_in,
                              void* d_out, int out_size) {
    const float* x    = (const float*)d_in[0];
    const float* w    = (const float*)d_in[1];
    const float* bias = (const float*)d_in[2];
    float* out        = (float*)d_out;

    cudaFuncSetAttribute(conv_mma_kernel, cudaFuncAttributeMaxDynamicSharedMemorySize, SMEM_DYN);

    transpose_x_kernel<<<dim3(98, 4, 32), dim3(32, 8)>>>(x);   // 3136/32 x 128/32 x 32
    transpose_w_kernel<<<dim3(36, 8), 256>>>(w);               // 1152 x 256
    conv_mma_kernel<<<dim3(784, 2), 256, SMEM_DYN>>>(bias, out);
}

// round 6
// speedup vs baseline: 5.1180x; 1.7075x over previous
#include <cuda_runtime.h>
#include <cuda_fp16.h>
#include <cstdint>

// Conv2DUF via legacy mma.sync FP16 implicit GEMM (compute_103-safe).
//   x: [32,128,56,56] f32   weight: [1152,256] f32   bias: [256]   out: [32,256,56,56]
// GEMM: M=100352 (pixels), N=256 (cout), K=1152 reordered k' = (kh*3+kw)*128 + c.
// Prepass (single kernel): x -> NHWC fp16 (g_xh), w -> [n][k'] fp16 (g_wh).
// Main: CTA 128x128, BK=64 (fp16, 128B rows), 18 stages, 8 warps x (32x64),
//       mma.m16n8k16.f16 (2x K/instr vs tf32 at same legacy HMMA rate),
//       3-buffer cp.async ring, one __syncthreads per stage.

namespace {
constexpr int HW = 3136;        // 56*56
constexpr int KT = 18;          // 1152/64
constexpr int ABUF = 16384;     // one A stage: 128 rows * 128B (64 fp16)
constexpr int BOFF = 3 * ABUF;
constexpr int SMEM_DYN = 6 * ABUF;   // 96 KB
constexpr int NXBLK = 12544;    // x-transpose blocks (98*4*32)
}

__device__ __half g_xh[32 * HW * 128];   // NHWC fp16 (25.7 MB)
__device__ __half g_wh[256 * 1152];      // [cout][k'] fp16

__device__ __forceinline__ uint32_t s2u(const void* p) {
    uint32_t a;
    asm("{.reg .u64 t; cvta.to.shared.u64 t, %1; cvt.u32.u64 %0, t;}" : "=r"(a) : "l"(p));
    return a;
}
__device__ __forceinline__ uint32_t swz(uint32_t o) { return o ^ ((o >> 3) & 0x70); }
__device__ __forceinline__ void cp16(uint32_t dst, const void* src, int sz) {
    asm volatile("cp.async.cg.shared.global [%0], [%1], 16, %2;" :: "r"(dst), "l"(src), "r"(sz));
}
__device__ __forceinline__ void ldsm4(uint32_t* r, uint32_t addr) {
    asm volatile("ldmatrix.sync.aligned.m8n8.x4.shared.b16 {%0,%1,%2,%3}, [%4];"
                 : "=r"(r[0]), "=r"(r[1]), "=r"(r[2]), "=r"(r[3]) : "r"(addr));
}
__device__ __forceinline__ void mma16(float* c, const uint32_t* a, uint32_t b0, uint32_t b1) {
    asm volatile("mma.sync.aligned.m16n8k16.row.col.f32.f16.f16.f32 "
                 "{%0,%1,%2,%3},{%4,%5,%6,%7},{%8,%9},{%0,%1,%2,%3};"
                 : "+f"(c[0]), "+f"(c[1]), "+f"(c[2]), "+f"(c[3])
                 : "r"(a[0]), "r"(a[1]), "r"(a[2]), "r"(a[3]), "r"(b0), "r"(b1));
}

// ---- prepass: x NCHW -> NHWC fp16, and w[k][n] -> [n][k'] fp16 ----
__global__ void prepass_kernel(const float* __restrict__ x, const float* __restrict__ w) {
    __shared__ float t[32][33];
    const int tid = threadIdx.x;
    const int tx = tid & 31, ty = tid >> 5;
    const int bx = blockIdx.x;
    if (bx < NXBLK) {
        // x transpose: 98 pixel-tiles x 4 channel-tiles x 32 images
        const int n  = bx / 392;
        const int r  = bx - n * 392;
        const int p0 = (r % 98) * 32;
        const int c0 = (r / 98) * 32;
        const float* xp = x + ((size_t)n * 128 + c0) * HW + p0;
#pragma unroll
        for (int i = ty; i < 32; i += 8)
            t[i][tx] = xp[(size_t)i * HW + tx];
        __syncthreads();
        __half* xo = g_xh + ((size_t)n * HW + p0) * 128 + c0;
#pragma unroll
        for (int i = ty; i < 32; i += 8)
            xo[(size_t)i * 128 + tx] = __float2half_rn(t[tx][i]);
    } else {
        // w transpose+reorder: k' = r*128 + c where k = c*9 + r
        const int idx = bx - NXBLK;          // 0..287
        const int kp0 = (idx % 36) * 32;
        const int n0  = (idx / 36) * 32;
        for (int i = ty; i < 32; i += 8) {
            int kp = kp0 + i;
            int rr = kp >> 7, c = kp & 127;
            t[i][tx] = w[(c * 9 + rr) * 256 + n0 + tx];
        }
        __syncthreads();
        for (int i = ty; i < 32; i += 8)
            g_wh[(size_t)(n0 + i) * 1152 + kp0 + tx] = __float2half_rn(t[tx][i]);
    }
}

// ---- main kernel ----
__global__ __launch_bounds__(256, 2)
void conv_mma_kernel(const float* __restrict__ bias, float* __restrict__ out) {
    extern __shared__ char smem[];
    const uint32_t sb = s2u(smem);          // A stages @0,16K,32K; B stages @48K,64K,80K
    const int tid = threadIdx.x, wid = tid >> 5, lid = tid & 31;
    const int bx = blockIdx.x;              // 784 M-tiles
    const int bn0 = blockIdx.y * 128;       // N tile

    // producer mapping: row = tid>>1 (0..127), qh picks which 4 of the 8 16B chunks
    const int arow = tid >> 1, qh = tid & 1;
    const int p = bx * 128 + arow;
    const int nimg = p / HW;
    const int rem = p - nimg * HW;
    const int yp = rem / 56, xp = rem - yp * 56;
    const __half* xrow = g_xh + ((size_t)nimg * HW + (yp - 1) * 56 + (xp - 1)) * 128;
    const __half* wrow = g_wh + (size_t)(bn0 + arow) * 1152;

    uint32_t dsto[4];
#pragma unroll
    for (int j = 0; j < 4; j++)
        dsto[j] = swz(arow * 128 + (qh * 4 + j) * 16);

    auto issue = [&](int kt, int buf) {
        const int r = kt >> 1;               // (kh,kw) index; stage covers 64 channels
        const int kh = r / 3, kw = r - kh * 3;
        const int cb = (kt & 1) * 64;        // channel block
        const bool ok = ((unsigned)(yp + kh - 1) < 56u) && ((unsigned)(xp + kw - 1) < 56u);
        const __half* asrc = ok ? (xrow + (kh * 56 + kw) * 128 + cb) : g_xh;
        const int sz = ok ? 16 : 0;
        const uint32_t ad = sb + buf * ABUF;
        const uint32_t bd = sb + BOFF + buf * ABUF;
        const __half* bsrc = wrow + kt * 64;
#pragma unroll
        for (int j = 0; j < 4; j++) {
            int q = qh * 4 + j;
            cp16(ad + dsto[j], asrc + (ok ? q * 8 : 0), sz);
            cp16(bd + dsto[j], bsrc + q * 8, 16);
        }
        asm volatile("cp.async.commit_group;" ::: "memory");
    };

    issue(0, 0);
    issue(1, 1);

    float acc[2][8][4];
#pragma unroll
    for (int i = 0; i < 2; i++)
#pragma unroll
        for (int j = 0; j < 8; j++)
#pragma unroll
            for (int q = 0; q < 4; q++) acc[i][j][q] = 0.f;

    const int m0  = (wid & 3) * 32;          // warp m-base
    const int n0w = (wid >> 2) * 64;         // warp n-base
    const int rowL = lid & 15;               // ldmatrix row lane
    const int colL = (lid >> 4) * 16;        // 16B column select

    int buf = 0, pbuf = 2;
    for (int kt = 0; kt < KT; kt++) {
        if (kt < KT - 1) asm volatile("cp.async.wait_group 1;" ::: "memory");
        else             asm volatile("cp.async.wait_group 0;" ::: "memory");
        __syncthreads();
        if (kt + 2 < KT) issue(kt + 2, pbuf);

        const uint32_t aT = sb + buf * ABUF;
        const uint32_t bT = sb + BOFF + buf * ABUF;
#pragma unroll
        for (int s = 0; s < 4; s++) {        // 4 x k16
            uint32_t a[2][4], b[4][4];
#pragma unroll
            for (int mi = 0; mi < 2; mi++)
                ldsm4(a[mi], aT + swz((m0 + mi * 16 + rowL) * 128 + s * 32 + colL));
#pragma unroll
            for (int nj = 0; nj < 4; nj++)
                ldsm4(b[nj], bT + swz((n0w + nj * 16 + rowL) * 128 + s * 32 + colL));
#pragma unroll
            for (int mi = 0; mi < 2; mi++)
#pragma unroll
                for (int ni = 0; ni < 8; ni++)
                    mma16(acc[mi][ni], a[mi], b[ni >> 1][ni & 1], b[ni >> 1][(ni & 1) + 2]);
        }
        buf  = (buf == 2)  ? 0 : buf + 1;
        pbuf = (pbuf == 2) ? 0 : pbuf + 1;
    }

    // ---- epilogue ----
    float bv[8][2];
#pragma unroll
    for (int ni = 0; ni < 8; ni++) {
        int co = bn0 + n0w + ni * 8 + (lid & 3) * 2;
        bv[ni][0] = bias[co];
        bv[ni][1] = bias[co + 1];
    }
#pragma unroll
    for (int mi = 0; mi < 2; mi++) {
        const int pg0 = bx * 128 + m0 + mi * 16 + (lid >> 2);
        const int pg1 = pg0 + 8;
        const int n0i = pg0 / HW, pix0 = pg0 - n0i * HW;
        const int n1i = pg1 / HW, pix1 = pg1 - n1i * HW;
        float* o0 = out + (size_t)n0i * 256 * HW + pix0;
        float* o1 = out + (size_t)n1i * 256 * HW + pix1;
#pragma unroll
        for (int ni = 0; ni < 8; ni++) {
            const int co = bn0 + n0w + ni * 8 + (lid & 3) * 2;
            o0[(size_t)co * HW]       = acc[mi][ni][0] + bv[ni][0];
            o0[(size_t)(co + 1) * HW] = acc[mi][ni][1] + bv[ni][1];
            o1[(size_t)co * HW]       = acc[mi][ni][2] + bv[ni][0];
            o1[(size_t)(co + 1) * HW] = acc[mi][ni][3] + bv[ni][1];
        }
    }
}

extern "C" void kernel_launch(void* const* d_in, const int* in_sizes, int n_in,
                              void* d_out, int out_size) {
    const float* x    = (const float*)d_in[0];
    const float* w    = (const float*)d_in[1];
    const float* bias = (const float*)d_in[2];
    float* out        = (float*)d_out;

    cudaFuncSetAttribute(conv_mma_kernel, cudaFuncAttributeMaxDynamicSharedMemorySize, SMEM_DYN);

    prepass_kernel<<<NXBLK + 288, 256>>>(x, w);
    conv_mma_kernel<<<dim3(784, 2), 256, SMEM_DYN>>>(bias, out);
}

// round 8
// speedup vs baseline: 5.1985x; 1.0157x over previous
#include <cuda_runtime.h>
#include <cuda_fp16.h>
#include <cstdint>

// Conv2DUF via legacy mma.sync FP16 implicit GEMM (compute_103-safe).
//   x: [32,128,56,56] f32   weight: [1152,256] f32   bias: [256]   out: [32,256,56,56]
// GEMM: M=100352 (pixels), N=256 (cout), K=1152 reordered k' = (kh*3+kw)*128 + c.
// Prepass (single kernel): x -> NHWC fp16 (g_xh), w -> [n][k'] fp16 (g_wh).
// Main: CTA 128x128, BK=64, 18 stages, 8 warps x (32x64), mma.m16n8k16.f16,
//       3-buffer cp.async ring, one sync per stage, smem-transposed coalesced epilogue.

namespace {
constexpr int HW = 3136;        // 56*56
constexpr int KT = 18;          // 1152/64
constexpr int ABUF = 16384;     // one A stage: 128 rows * 128B (64 fp16)
constexpr int BOFF = 3 * ABUF;
constexpr int SMEM_DYN = 6 * ABUF;   // 96 KB (also covers 128*132*4 = 67.6 KB epilogue scratch)
constexpr int NXBLK = 12544;    // x-transpose blocks (98*4*32)
constexpr int EPAD = 132;       // epilogue scratch row pitch (floats)
}

__device__ __half g_xh[32 * HW * 128];   // NHWC fp16 (25.7 MB)
__device__ __half g_wh[256 * 1152];      // [cout][k'] fp16

__device__ __forceinline__ uint32_t s2u(const void* p) {
    uint32_t a;
    asm("{.reg .u64 t; cvta.to.shared.u64 t, %1; cvt.u32.u64 %0, t;}" : "=r"(a) : "l"(p));
    return a;
}
__device__ __forceinline__ uint32_t swz(uint32_t o) { return o ^ ((o >> 3) & 0x70); }
__device__ __forceinline__ void cp16(uint32_t dst, const void* src, int sz) {
    asm volatile("cp.async.cg.shared.global [%0], [%1], 16, %2;" :: "r"(dst), "l"(src), "r"(sz));
}
__device__ __forceinline__ void ldsm4(uint32_t* r, uint32_t addr) {
    asm volatile("ldmatrix.sync.aligned.m8n8.x4.shared.b16 {%0,%1,%2,%3}, [%4];"
                 : "=r"(r[0]), "=r"(r[1]), "=r"(r[2]), "=r"(r[3]) : "r"(addr));
}
__device__ __forceinline__ void mma16(float* c, const uint32_t* a, uint32_t b0, uint32_t b1) {
    asm volatile("mma.sync.aligned.m16n8k16.row.col.f32.f16.f16.f32 "
                 "{%0,%1,%2,%3},{%4,%5,%6,%7},{%8,%9},{%0,%1,%2,%3};"
                 : "+f"(c[0]), "+f"(c[1]), "+f"(c[2]), "+f"(c[3])
                 : "r"(a[0]), "r"(a[1]), "r"(a[2]), "r"(a[3]), "r"(b0), "r"(b1));
}

// ---- prepass: x NCHW -> NHWC fp16, and w[k][n] -> [n][k'] fp16 ----
__global__ void prepass_kernel(const float* __restrict__ x, const float* __restrict__ w) {
    __shared__ float t[32][33];
    const int tid = threadIdx.x;
    const int tx = tid & 31, ty = tid >> 5;
    const int bx = blockIdx.x;
    if (bx < NXBLK) {
        const int n  = bx / 392;
        const int r  = bx - n * 392;
        const int p0 = (r % 98) * 32;
        const int c0 = (r / 98) * 32;
        const float* xp = x + ((size_t)n * 128 + c0) * HW + p0;
#pragma unroll
        for (int i = ty; i < 32; i += 8)
            t[i][tx] = xp[(size_t)i * HW + tx];
        __syncthreads();
        __half* xo = g_xh + ((size_t)n * HW + p0) * 128 + c0;
#pragma unroll
        for (int i = ty; i < 32; i += 8)
            xo[(size_t)i * 128 + tx] = __float2half_rn(t[tx][i]);
    } else {
        const int idx = bx - NXBLK;          // 0..287
        const int kp0 = (idx % 36) * 32;
        const int n0  = (idx / 36) * 32;
        for (int i = ty; i < 32; i += 8) {
            int kp = kp0 + i;
            int rr = kp >> 7, c = kp & 127;
            t[i][tx] = w[(c * 9 + rr) * 256 + n0 + tx];
        }
        __syncthreads();
        for (int i = ty; i < 32; i += 8)
            g_wh[(size_t)(n0 + i) * 1152 + kp0 + tx] = __float2half_rn(t[tx][i]);
    }
}

// ---- main kernel ----
__global__ __launch_bounds__(256, 2)
void conv_mma_kernel(const float* __restrict__ bias, float* __restrict__ out) {
    extern __shared__ char smem[];
    const uint32_t sb = s2u(smem);          // A stages @0,16K,32K; B stages @48K,64K,80K
    const int tid = threadIdx.x, wid = tid >> 5, lid = tid & 31;
    const int bx = blockIdx.x;              // 784 M-tiles
    const int bn0 = blockIdx.y * 128;       // N tile

    // producer mapping
    const int arow = tid >> 1, qh = tid & 1;
    const int p = bx * 128 + arow;
    const int nimg = p / HW;
    const int rem = p - nimg * HW;
    const int yp = rem / 56, xp = rem - yp * 56;
    const __half* xrow = g_xh + ((size_t)nimg * HW + (yp - 1) * 56 + (xp - 1)) * 128;
    const __half* wrow = g_wh + (size_t)(bn0 + arow) * 1152;

    uint32_t dsto[4];
#pragma unroll
    for (int j = 0; j < 4; j++)
        dsto[j] = swz(arow * 128 + (qh * 4 + j) * 16);

    auto issue = [&](int kt, int buf) {
        const int r = kt >> 1;
        const int kh = r / 3, kw = r - kh * 3;
        const int cb = (kt & 1) * 64;
        const bool ok = ((unsigned)(yp + kh - 1) < 56u) && ((unsigned)(xp + kw - 1) < 56u);
        const __half* asrc = ok ? (xrow + (kh * 56 + kw) * 128 + cb) : g_xh;
        const int sz = ok ? 16 : 0;
        const uint32_t ad = sb + buf * ABUF;
        const uint32_t bd = sb + BOFF + buf * ABUF;
        const __half* bsrc = wrow + kt * 64;
#pragma unroll
        for (int j = 0; j < 4; j++) {
            int q = qh * 4 + j;
            cp16(ad + dsto[j], asrc + (ok ? q * 8 : 0), sz);
            cp16(bd + dsto[j], bsrc + q * 8, 16);
        }
        asm volatile("cp.async.commit_group;" ::: "memory");
    };

    issue(0, 0);
    issue(1, 1);

    float acc[2][8][4];
#pragma unroll
    for (int i = 0; i < 2; i++)
#pragma unroll
        for (int j = 0; j < 8; j++)
#pragma unroll
            for (int q = 0; q < 4; q++) acc[i][j][q] = 0.f;

    const int m0  = (wid & 3) * 32;
    const int n0w = (wid >> 2) * 64;
    const int rowL = lid & 15;
    const int colL = (lid >> 4) * 16;

    int buf = 0, pbuf = 2;
    for (int kt = 0; kt < KT; kt++) {
        if (kt < KT - 1) asm volatile("cp.async.wait_group 1;" ::: "memory");
        else             asm volatile("cp.async.wait_group 0;" ::: "memory");
        __syncthreads();
        if (kt + 2 < KT) issue(kt + 2, pbuf);

        const uint32_t aT = sb + buf * ABUF;
        const uint32_t bT = sb + BOFF + buf * ABUF;
#pragma unroll
        for (int s = 0; s < 4; s++) {
            uint32_t a[2][4], b[4][4];
#pragma unroll
            for (int mi = 0; mi < 2; mi++)
                ldsm4(a[mi], aT + swz((m0 + mi * 16 + rowL) * 128 + s * 32 + colL));
#pragma unroll
            for (int nj = 0; nj < 4; nj++)
                ldsm4(b[nj], bT + swz((n0w + nj * 16 + rowL) * 128 + s * 32 + colL));
#pragma unroll
            for (int mi = 0; mi < 2; mi++)
#pragma unroll
                for (int ni = 0; ni < 8; ni++)
                    mma16(acc[mi][ni], a[mi], b[ni >> 1][ni & 1], b[ni >> 1][(ni & 1) + 2]);
        }
        buf  = (buf == 2)  ? 0 : buf + 1;
        pbuf = (pbuf == 2) ? 0 : pbuf + 1;
    }

    // ---- epilogue: acc -> smem [channel][pixel] -> coalesced float4 NCHW stores ----
    __syncthreads();                         // all ldsm reads done; smem ring is free
    float* sc = reinterpret_cast<float*>(smem);   // [128][EPAD] floats (67.6 KB)

#pragma unroll
    for (int mi = 0; mi < 2; mi++) {
        const int mr = m0 + mi * 16 + (lid >> 2);
#pragma unroll
        for (int ni = 0; ni < 8; ni++) {
            const int c0 = n0w + ni * 8 + (lid & 3) * 2;
            sc[c0 * EPAD + mr]           = acc[mi][ni][0];
            sc[(c0 + 1) * EPAD + mr]     = acc[mi][ni][1];
            sc[c0 * EPAD + mr + 8]       = acc[mi][ni][2];
            sc[(c0 + 1) * EPAD + mr + 8] = acc[mi][ni][3];
        }
    }
    __syncthreads();

    const int base = bx * 128;
    const int img0 = base / HW;
    const int off0 = base - img0 * HW;
#pragma unroll
    for (int j = 0; j < 16; j++) {
        const int c = wid * 16 + j;
        float4 v = *reinterpret_cast<const float4*>(&sc[c * EPAD + lid * 4]);
        const float bb = bias[bn0 + c];
        v.x += bb; v.y += bb; v.z += bb; v.w += bb;
        int pix = off0 + lid * 4;
        int img = img0;
        if (pix >= HW) { pix -= HW; img++; }
        *reinterpret_cast<float4*>(out + ((size_t)(img * 256 + bn0 + c)) * HW + pix) = v;
    }
}

extern "C" void kernel_launch(void* const* d_in, const int* in_sizes, int n_in,
                              void* d_out, int out_size) {
    const float* x    = (const float*)d_in[0];
    const float* w    = (const float*)d_in[1];
    const float* bias = (const float*)d_in[2];
    float* out        = (float*)d_out;

    cudaFuncSetAttribute(conv_mma_kernel, cudaFuncAttributeMaxDynamicSharedMemorySize, SMEM_DYN);

    prepass_kernel<<<NXBLK + 288, 256>>>(x, w);
    conv_mma_kernel<<<dim3(784, 2), 256, SMEM_DYN>>>(bias, out);
}

// round 9
// speedup vs baseline: 5.2958x; 1.0187x over previous
#include <cuda_runtime.h>
#include <cuda_fp16.h>
#include <cstdint>

// Conv2DUF via legacy mma.sync FP16 implicit GEMM (compute_103-safe).
//   x: [32,128,56,56] f32   weight: [1152,256] f32   bias: [256]   out: [32,256,56,56]
// GEMM: M=100352 (pixels), N=256 (cout), K=1152 reordered k' = (kh*3+kw)*128 + c.
// Prepass (single kernel): x -> NHWC fp16 (g_xh, vectorized stores), w -> [n][k'] fp16.
// Main: CTA 128x128, BK=64, 18 stages, 8 warps x (32x64), mma.m16n8k16.f16,
//       3-buffer cp.async ring, one sync per stage, fragment double-buffering
//       across k16 sub-steps, smem-transposed coalesced epilogue.

namespace {
constexpr int HW = 3136;        // 56*56
constexpr int KT = 18;          // 1152/64
constexpr int ABUF = 16384;     // one A stage: 128 rows * 128B (64 fp16)
constexpr int BOFF = 3 * ABUF;
constexpr int SMEM_DYN = 6 * ABUF;   // 96 KB (also covers epilogue scratch)
constexpr int NXBLK = 12544;    // x-transpose blocks (98*4*32)
constexpr int EPAD = 132;       // epilogue scratch row pitch (floats)
}

__device__ __half g_xh[32 * HW * 128];   // NHWC fp16 (25.7 MB)
__device__ __half g_wh[256 * 1152];      // [cout][k'] fp16

struct alignas(8) Half4 { __half2 a, b; };

__device__ __forceinline__ uint32_t s2u(const void* p) {
    uint32_t a;
    asm("{.reg .u64 t; cvta.to.shared.u64 t, %1; cvt.u32.u64 %0, t;}" : "=r"(a) : "l"(p));
    return a;
}
__device__ __forceinline__ uint32_t swz(uint32_t o) { return o ^ ((o >> 3) & 0x70); }
__device__ __forceinline__ void cp16(uint32_t dst, const void* src, int sz) {
    asm volatile("cp.async.cg.shared.global [%0], [%1], 16, %2;" :: "r"(dst), "l"(src), "r"(sz));
}
__device__ __forceinline__ void ldsm4(uint32_t* r, uint32_t addr) {
    asm volatile("ldmatrix.sync.aligned.m8n8.x4.shared.b16 {%0,%1,%2,%3}, [%4];"
                 : "=r"(r[0]), "=r"(r[1]), "=r"(r[2]), "=r"(r[3]) : "r"(addr));
}
__device__ __forceinline__ void mma16(float* c, const uint32_t* a, uint32_t b0, uint32_t b1) {
    asm volatile("mma.sync.aligned.m16n8k16.row.col.f32.f16.f16.f32 "
                 "{%0,%1,%2,%3},{%4,%5,%6,%7},{%8,%9},{%0,%1,%2,%3};"
                 : "+f"(c[0]), "+f"(c[1]), "+f"(c[2]), "+f"(c[3])
                 : "r"(a[0]), "r"(a[1]), "r"(a[2]), "r"(a[3]), "r"(b0), "r"(b1));
}

// ---- prepass: x NCHW -> NHWC fp16 (8B stores), and w[k][n] -> [n][k'] fp16 ----
__global__ void prepass_kernel(const float* __restrict__ x, const float* __restrict__ w) {
    __shared__ float t[32][33];
    const int tid = threadIdx.x;
    const int tx = tid & 31, ty = tid >> 5;
    const int bx = blockIdx.x;
    if (bx < NXBLK) {
        const int n  = bx / 392;
        const int r  = bx - n * 392;
        const int p0 = (r % 98) * 32;
        const int c0 = (r / 98) * 32;
        const float* xp = x + ((size_t)n * 128 + c0) * HW + p0;
#pragma unroll
        for (int i = ty; i < 32; i += 8)
            t[i][tx] = xp[(size_t)i * HW + tx];     // t[ch][pix]
        __syncthreads();
        // each thread: 1 pixel row (prow), 4 channels (cq*4..+3), one 8B store
        const int prow = tid >> 3;                  // 0..31
        const int cq   = tid & 7;                   // 0..7
        __half h0 = __float2half_rn(t[cq * 4 + 0][prow]);
        __half h1 = __float2half_rn(t[cq * 4 + 1][prow]);
        __half h2 = __float2half_rn(t[cq * 4 + 2][prow]);
        __half h3 = __float2half_rn(t[cq * 4 + 3][prow]);
        Half4 v{__halves2half2(h0, h1), __halves2half2(h2, h3)};
        __half* xo = g_xh + ((size_t)n * HW + p0 + prow) * 128 + c0 + cq * 4;
        *reinterpret_cast<Half4*>(xo) = v;
    } else {
        const int idx = bx - NXBLK;          // 0..287
        const int kp0 = (idx % 36) * 32;
        const int n0  = (idx / 36) * 32;
        for (int i = ty; i < 32; i += 8) {
            int kp = kp0 + i;
            int rr = kp >> 7, c = kp & 127;
            t[i][tx] = w[(c * 9 + rr) * 256 + n0 + tx];
        }
        __syncthreads();
        for (int i = ty; i < 32; i += 8)
            g_wh[(size_t)(n0 + i) * 1152 + kp0 + tx] = __float2half_rn(t[tx][i]);
    }
}

// ---- main kernel ----
__global__ __launch_bounds__(256, 2)
void conv_mma_kernel(const float* __restrict__ bias, float* __restrict__ out) {
    extern __shared__ char smem[];
    const uint32_t sb = s2u(smem);          // A stages @0,16K,32K; B stages @48K,64K,80K
    const int tid = threadIdx.x, wid = tid >> 5, lid = tid & 31;
    const int bx = blockIdx.x;              // 784 M-tiles
    const int bn0 = blockIdx.y * 128;       // N tile

    // producer mapping
    const int arow = tid >> 1, qh = tid & 1;
    const int p = bx * 128 + arow;
    const int nimg = p / HW;
    const int rem = p - nimg * HW;
    const int yp = rem / 56, xp = rem - yp * 56;
    const __half* xrow = g_xh + ((size_t)nimg * HW + (yp - 1) * 56 + (xp - 1)) * 128;
    const __half* wrow = g_wh + (size_t)(bn0 + arow) * 1152;

    uint32_t dsto[4];
#pragma unroll
    for (int j = 0; j < 4; j++)
        dsto[j] = swz(arow * 128 + (qh * 4 + j) * 16);

    auto issue = [&](int kt, int buf) {
        const int r = kt >> 1;
        const int kh = r / 3, kw = r - kh * 3;
        const int cb = (kt & 1) * 64;
        const bool ok = ((unsigned)(yp + kh - 1) < 56u) && ((unsigned)(xp + kw - 1) < 56u);
        const __half* asrc = ok ? (xrow + (kh * 56 + kw) * 128 + cb) : g_xh;
        const int sz = ok ? 16 : 0;
        const uint32_t ad = sb + buf * ABUF;
        const uint32_t bd = sb + BOFF + buf * ABUF;
        const __half* bsrc = wrow + kt * 64;
#pragma unroll
        for (int j = 0; j < 4; j++) {
            int q = qh * 4 + j;
            cp16(ad + dsto[j], asrc + (ok ? q * 8 : 0), sz);
            cp16(bd + dsto[j], bsrc + q * 8, 16);
        }
        asm volatile("cp.async.commit_group;" ::: "memory");
    };

    issue(0, 0);
    issue(1, 1);

    float acc[2][8][4];
#pragma unroll
    for (int i = 0; i < 2; i++)
#pragma unroll
        for (int j = 0; j < 8; j++)
#pragma unroll
            for (int q = 0; q < 4; q++) acc[i][j][q] = 0.f;

    const int m0  = (wid & 3) * 32;
    const int n0w = (wid >> 2) * 64;
    const int rowL = lid & 15;
    const int colL = (lid >> 4) * 16;

    int buf = 0, pbuf = 2;
    for (int kt = 0; kt < KT; kt++) {
        if (kt < KT - 1) asm volatile("cp.async.wait_group 1;" ::: "memory");
        else             asm volatile("cp.async.wait_group 0;" ::: "memory");
        __syncthreads();

        const uint32_t aT = sb + buf * ABUF;
        const uint32_t bT = sb + BOFF + buf * ABUF;

        uint32_t a[2][2][4], b[2][4][4];    // double-buffered fragments
        // prefetch s=0
#pragma unroll
        for (int mi = 0; mi < 2; mi++)
            ldsm4(a[0][mi], aT + swz((m0 + mi * 16 + rowL) * 128 + colL));
#pragma unroll
        for (int nj = 0; nj < 4; nj++)
            ldsm4(b[0][nj], bT + swz((n0w + nj * 16 + rowL) * 128 + colL));

        if (kt + 2 < KT) issue(kt + 2, pbuf);   // producer overlaps tensor work

#pragma unroll
        for (int s = 0; s < 4; s++) {
            const int cur = s & 1, nxt = cur ^ 1;
            if (s < 3) {                        // prefetch s+1 before s's MMAs
#pragma unroll
                for (int mi = 0; mi < 2; mi++)
                    ldsm4(a[nxt][mi], aT + swz((m0 + mi * 16 + rowL) * 128 + (s + 1) * 32 + colL));
#pragma unroll
                for (int nj = 0; nj < 4; nj++)
                    ldsm4(b[nxt][nj], bT + swz((n0w + nj * 16 + rowL) * 128 + (s + 1) * 32 + colL));
            }
#pragma unroll
            for (int mi = 0; mi < 2; mi++)
#pragma unroll
                for (int ni = 0; ni < 8; ni++)
                    mma16(acc[mi][ni], a[cur][mi],
                          b[cur][ni >> 1][ni & 1], b[cur][ni >> 1][(ni & 1) + 2]);
        }
        buf  = (buf == 2)  ? 0 : buf + 1;
        pbuf = (pbuf == 2) ? 0 : pbuf + 1;
    }

    // ---- epilogue: acc -> smem [channel][pixel] -> coalesced float4 NCHW stores ----
    __syncthreads();
    float* sc = reinterpret_cast<float*>(smem);   // [128][EPAD] floats

#pragma unroll
    for (int mi = 0; mi < 2; mi++) {
        const int mr = m0 + mi * 16 + (lid >> 2);
#pragma unroll
        for (int ni = 0; ni < 8; ni++) {
            const int c0 = n0w + ni * 8 + (lid & 3) * 2;
            sc[c0 * EPAD + mr]           = acc[mi][ni][0];
            sc[(c0 + 1) * EPAD + mr]     = acc[mi][ni][1];
            sc[c0 * EPAD + mr + 8]       = acc[mi][ni][2];
            sc[(c0 + 1) * EPAD + mr + 8] = acc[mi][ni][3];
        }
    }
    __syncthreads();

    const int base = bx * 128;
    const int img0 = base / HW;
    const int off0 = base - img0 * HW;
#pragma unroll
    for (int j = 0; j < 16; j++) {
        const int c = wid * 16 + j;
        float4 v = *reinterpret_cast<const float4*>(&sc[c * EPAD + lid * 4]);
        const float bb = bias[bn0 + c];
        v.x += bb; v.y += bb; v.z += bb; v.w += bb;
        int pix = off0 + lid * 4;
        int img = img0;
        if (pix >= HW) { pix -= HW; img++; }
        *reinterpret_cast<float4*>(out + ((size_t)(img * 256 + bn0 + c)) * HW + pix) = v;
    }
}

extern "C" void kernel_launch(void* const* d_in, const int* in_sizes, int n_in,
                              void* d_out, int out_size) {
    const float* x    = (const float*)d_in[0];
    const float* w    = (const float*)d_in[1];
    const float* bias = (const float*)d_in[2];
    float* out        = (float*)d_out;

    cudaFuncSetAttribute(conv_mma_kernel, cudaFuncAttributeMaxDynamicSharedMemorySize, SMEM_DYN);

    prepass_kernel<<<NXBLK + 288, 256>>>(x, w);
    conv_mma_kernel<<<dim3(784, 2), 256, SMEM_DYN>>>(bias, out);
}